// round 5
// baseline (speedup 1.0000x reference)
#include <cuda_runtime.h>
#include <cstdint>

// Identity op: reference output == input X.
// HBM copy tuned for L2 residency across graph replays:
//   - src (128 MiB) nearly fits in L2 (~126 MB). Reads use __ldcg (cache in
//     L2, bypass L1) so src lines persist between replays.
//   - Writes use __stcs (evict-first) so the 128 MiB write stream does not
//     evict the src working set.
//   - VPT=8 float4 per thread (128 B), front-batched loads for MLP.

constexpr int VPT = 8;  // float4 per thread

__global__ void copy_l2res_kernel(const float4* __restrict__ src,
                                  float4* __restrict__ dst,
                                  long long n4) {
    long long base = (long long)blockIdx.x * (blockDim.x * VPT) + threadIdx.x;

    float4 v[VPT];
    #pragma unroll
    for (int j = 0; j < VPT; j++) {
        long long i = base + (long long)j * blockDim.x;
        if (i < n4) v[j] = __ldcg(src + i);     // keep in L2
    }
    #pragma unroll
    for (int j = 0; j < VPT; j++) {
        long long i = base + (long long)j * blockDim.x;
        if (i < n4) __stcs(dst + i, v[j]);      // evict-first write
    }
}

// Scalar tail fallback (not expected: n = 2^25 floats, 16B-divisible).
__global__ void copy_f1_kernel(const float* __restrict__ src,
                               float* __restrict__ dst,
                               long long n) {
    long long i = (long long)blockIdx.x * blockDim.x + threadIdx.x;
    if (i < n) dst[i] = src[i];
}

extern "C" void kernel_launch(void* const* d_in, const int* in_sizes, int n_in,
                              void* d_out, int out_size) {
    const float* x = (const float*)d_in[0];
    float* out = (float*)d_out;
    long long n = (long long)out_size;   // 33,554,432 floats expected

    long long n4 = n >> 2;
    long long rem = n - (n4 << 2);

    if (n4 > 0) {
        const int threads = 256;
        const long long per_block = (long long)threads * VPT;  // 2048 float4
        long long blocks_ll = (n4 + per_block - 1) / per_block; // 4096 expected
        int blocks = (blocks_ll > 1048576LL) ? 1048576 : (int)blocks_ll;
        copy_l2res_kernel<<<blocks, threads>>>((const float4*)x, (float4*)out, n4);
    }
    if (rem > 0) {
        const float* s = x + (n4 << 2);
        float* d = out + (n4 << 2);
        copy_f1_kernel<<<1, 256>>>(s, d, rem);
    }
}